// round 7
// baseline (speedup 1.0000x reference)
#include <cuda_runtime.h>
#include <cstdint>

// Problem constants (fixed shapes per reference setup_inputs)
#define NCLASS 19
#define HW (512 * 1024)            // 524288 pixels per (b,c) plane
#define NBATCH 8
#define NPIX (NBATCH * HW)         // 4194304 pixels
#define NVEC (NPIX / 4)            // 1048576 float4 groups
#define THREADS 256
#define GRID 1024
#define STREAMS 4                  // independent argmax chains per thread
#define OFFSET (GRID * THREADS)    // 262144 float4 between streams (= 2 batches)
// GRID*THREADS*STREAMS == NVEC exactly

// Scratch counters in device globals (no allocation allowed).
// Zero-initialized at load; finalizing block resets them -> clean per replay.
__device__ unsigned int g_pred_cnt[NCLASS];
__device__ unsigned int g_true_cnt[NCLASS];
__device__ unsigned int g_inter_cnt[NCLASS];
__device__ unsigned int g_ticket;

__global__ __launch_bounds__(THREADS)
void iou_fused_kernel(const float* __restrict__ preds,
                      const int*   __restrict__ targets,
                      float*       __restrict__ out) {
    __shared__ unsigned int s_pred[NCLASS];
    __shared__ unsigned int s_true[NCLASS];
    __shared__ unsigned int s_inter[NCLASS];
    __shared__ bool s_is_last;

    const int t = threadIdx.x;
    if (t < NCLASS) {
        s_pred[t]  = 0u;
        s_true[t]  = 0u;
        s_inter[t] = 0u;
    }
    __syncthreads();

    const size_t ch_stride4 = HW / 4;      // float4 stride between channels
    const unsigned int tid = blockIdx.x * THREADS + t;

    // 4 independent stream bases. Stream k handles float4 index tid + k*OFFSET.
    // preds elem offset for pixel i, channel c: i + (i/HW)*(C-1)*HW + c*HW
    const float4* p[STREAMS];
#pragma unroll
    for (int k = 0; k < STREAMS; ++k) {
        const unsigned int vidx = tid + k * OFFSET;
        const unsigned int i = vidx * 4;
        const unsigned int b = i / HW;                    // shift (HW pow2)
        const size_t base = (size_t)i + (size_t)b * (size_t)(NCLASS - 1) * HW;
        p[k] = reinterpret_cast<const float4*>(preds + base);
    }

    // Independent argmax state per stream: 4 pixels each.
    float4 best[STREAMS];
    int bi[STREAMS][4];
#pragma unroll
    for (int k = 0; k < STREAMS; ++k) {
        best[k] = p[k][0];
        bi[k][0] = bi[k][1] = bi[k][2] = bi[k][3] = 0;
    }

    // Channel loop: the 4 loads per channel belong to independent chains, so
    // they batch (MLP >= 4) and pipeline across channel iterations.
#pragma unroll
    for (int c = 1; c < NCLASS; ++c) {
        float4 v[STREAMS];
#pragma unroll
        for (int k = 0; k < STREAMS; ++k)
            v[k] = p[k][(size_t)c * ch_stride4];
#pragma unroll
        for (int k = 0; k < STREAMS; ++k) {
            bool gx = v[k].x > best[k].x;
            bool gy = v[k].y > best[k].y;
            bool gz = v[k].z > best[k].z;
            bool gw = v[k].w > best[k].w;
            best[k].x = gx ? v[k].x : best[k].x;  bi[k][0] = gx ? c : bi[k][0];
            best[k].y = gy ? v[k].y : best[k].y;  bi[k][1] = gy ? c : bi[k][1];
            best[k].z = gz ? v[k].z : best[k].z;  bi[k][2] = gz ? c : bi[k][2];
            best[k].w = gw ? v[k].w : best[k].w;  bi[k][3] = gw ? c : bi[k][3];
        }
    }

    // Histogram phase (shared atomics)
#pragma unroll
    for (int k = 0; k < STREAMS; ++k) {
        const int4 tg = reinterpret_cast<const int4*>(targets)[tid + k * OFFSET];

        atomicAdd(&s_pred[bi[k][0]], 1u);
        atomicAdd(&s_pred[bi[k][1]], 1u);
        atomicAdd(&s_pred[bi[k][2]], 1u);
        atomicAdd(&s_pred[bi[k][3]], 1u);

        atomicAdd(&s_true[tg.x], 1u);
        atomicAdd(&s_true[tg.y], 1u);
        atomicAdd(&s_true[tg.z], 1u);
        atomicAdd(&s_true[tg.w], 1u);

        if (bi[k][0] == tg.x) atomicAdd(&s_inter[bi[k][0]], 1u);
        if (bi[k][1] == tg.y) atomicAdd(&s_inter[bi[k][1]], 1u);
        if (bi[k][2] == tg.z) atomicAdd(&s_inter[bi[k][2]], 1u);
        if (bi[k][3] == tg.w) atomicAdd(&s_inter[bi[k][3]], 1u);
    }

    __syncthreads();

    // ---- global accumulate + fence ----
    if (t < NCLASS) {
        if (s_pred[t])  atomicAdd(&g_pred_cnt[t],  s_pred[t]);
        if (s_true[t])  atomicAdd(&g_true_cnt[t],  s_true[t]);
        if (s_inter[t]) atomicAdd(&g_inter_cnt[t], s_inter[t]);
        __threadfence();
    }
    __syncthreads();

    // ---- ticket: last block finalizes ----
    if (t == 0) {
        unsigned int old = atomicAdd(&g_ticket, 1u);
        s_is_last = (old == (unsigned int)(gridDim.x - 1));
    }
    __syncthreads();

    if (s_is_last) {
        __shared__ float iou[NCLASS];
        if (t < NCLASS) {
            unsigned int inter = *(volatile unsigned int*)&g_inter_cnt[t];
            unsigned int pc    = *(volatile unsigned int*)&g_pred_cnt[t];
            unsigned int tc    = *(volatile unsigned int*)&g_true_cnt[t];
            unsigned int uni = pc + tc - inter;
            float v = (tc > 0u) ? ((float)inter / (float)max(uni, 1u)) : 0.0f;
            iou[t] = v;
            if (t >= 1) out[t - 1] = v;
            g_pred_cnt[t]  = 0u;
            g_true_cnt[t]  = 0u;
            g_inter_cnt[t] = 0u;
        }
        __syncthreads();
        if (t == 0) {
            float s = 0.0f;
#pragma unroll
            for (int c = 1; c < NCLASS; ++c) s += iou[c];
            out[NCLASS - 1] = s / (float)(NCLASS - 1);
            g_ticket = 0u;
        }
    }
}

extern "C" void kernel_launch(void* const* d_in, const int* in_sizes, int n_in,
                              void* d_out, int out_size) {
    const float* preds   = (const float*)d_in[0];
    const int*   targets = (const int*)d_in[1];
    float*       out     = (float*)d_out;

    iou_fused_kernel<<<GRID, THREADS>>>(preds, targets, out);
}